// round 1
// baseline (speedup 1.0000x reference)
#include <cuda_runtime.h>
#include <math.h>

#define BB 2
#define NN 8192
#define CC 32
#define RR 64
#define G3 64
#define MM (RR*G3)        /* 4096 queries per batch */
#define BM (BB*MM)        /* 8192 total queries */
#define NS1 16
#define NS2 32
#define RADIUS_C 0.8f
#define MIN_R_C 0.01f
#define DIV_COEF_C 10.0f
#define EPS_C 1e-5f

// -------- scratch (device globals; no allocation allowed) --------
__device__ float g_bufA[BM*NS2*64];   // 64 MiB: y1 (stage1 L0, stride 512) / y3 (stage2 L0, stride 2048)
__device__ float g_bufB[BM*NS2*64];   // 64 MiB: y2 / y4
__device__ int   g_idx[BM*NS2];       // neighbor indices (stride NS2 for both stages)
__device__ unsigned char g_empty[BM];
__device__ float g_w[BM*NS2];         // sigmoid weights (stage2)
__device__ float g_rad[BB*RR];        // learned per-roi radius
__device__ float g_sum[4][64];
__device__ float g_sq[4][64];
__device__ float g_scale[4][64];
__device__ float g_shift[4][64];

// -------- zero BN stat accumulators (must run each graph replay) --------
__global__ void k_zero() {
    int t = threadIdx.x;
    if (t < 64) {
        #pragma unroll
        for (int j = 0; j < 4; j++) { g_sum[j][t] = 0.f; g_sq[j][t] = 0.f; }
    }
}

// -------- ball query: one warp per query, first-found ascending indices --------
__global__ void k_bq(const float* __restrict__ xyz, const float* __restrict__ q,
                     int nsample, int use_rad) {
    int wq   = (blockIdx.x * blockDim.x + threadIdx.x) >> 5;
    int lane = threadIdx.x & 31;
    if (wq >= BM) return;
    int b = wq / MM, m = wq % MM;
    float qx = q[wq*3+0], qy = q[wq*3+1], qz = q[wq*3+2];
    float r  = use_rad ? g_rad[b*RR + m/G3] : RADIUS_C;
    float r2 = r * r;
    const float* xb = xyz + (size_t)b*NN*3;

    int cnt = 0, firstIdx = 0;
    bool have = false;
    for (int j0 = 0; j0 < NN; j0 += 32) {
        int i = j0 + lane;
        float dx = xb[i*3+0]-qx, dy = xb[i*3+1]-qy, dz = xb[i*3+2]-qz;
        float d2 = fmaf(dx,dx, fmaf(dy,dy, dz*dz));
        bool valid = d2 < r2;
        unsigned mask = __ballot_sync(0xffffffffu, valid);
        if (mask) {
            if (!have) { firstIdx = j0 + __ffs(mask) - 1; have = true; }
            int pos = cnt + __popc(mask & ((1u << lane) - 1u));
            if (valid && pos < nsample) g_idx[wq*NS2 + pos] = i;
            cnt += __popc(mask);
            if (cnt >= nsample) break;
        }
    }
    if (!have) {
        if (lane == 0) g_empty[wq] = 1;
        if (lane < nsample) g_idx[wq*NS2 + lane] = 0;
    } else {
        if (lane == 0) g_empty[wq] = 0;
        int cc = cnt < nsample ? cnt : nsample;
        if (lane >= cc && lane < nsample) g_idx[wq*NS2 + lane] = firstIdx;
    }
}

// -------- stage1 layer0: gather + conv 35->32, accumulate BN stats --------
__global__ void k_conv_p0(const float* __restrict__ xyz, const float* __restrict__ feats,
                          const float* __restrict__ rois, const float* __restrict__ W) {
    __shared__ float xs[NS1][36];
    __shared__ float Ws[35*32];
    __shared__ float ssum[32], ssq[32];
    int bm = blockIdx.x, b = bm / MM;
    int tid = threadIdx.x, s = tid >> 5, c = tid & 31;
    for (int i = tid; i < 35*32; i += 512) Ws[i] = W[i];
    if (tid < 32) { ssum[tid] = 0.f; ssq[tid] = 0.f; }
    bool emp = g_empty[bm] != 0;
    int pidx = g_idx[bm*NS2 + s];
    if (c < 3) xs[s][c]   = emp ? 0.f : xyz[((size_t)b*NN + pidx)*3 + c] - rois[bm*3 + c];
    xs[s][3+c]            = emp ? 0.f : feats[((size_t)b*NN + pidx)*CC + c];
    __syncthreads();
    float y = 0.f;
    #pragma unroll
    for (int k = 0; k < 35; k++) y = fmaf(xs[s][k], Ws[k*32 + c], y);
    g_bufA[bm*512 + tid] = y;
    atomicAdd(&ssum[c], y);
    atomicAdd(&ssq[c], y*y);
    __syncthreads();
    if (tid < 32) { atomicAdd(&g_sum[0][tid], ssum[tid]); atomicAdd(&g_sq[0][tid], ssq[tid]); }
}

// -------- BN finalize: (sum,sumsq) -> (scale,shift) --------
__global__ void k_fin(int layer, int C, float cnt,
                      const float* __restrict__ g, const float* __restrict__ bet) {
    int c = threadIdx.x;
    if (c >= C) return;
    float mean = g_sum[layer][c] / cnt;
    float var  = g_sq[layer][c] / cnt - mean*mean;
    float sc   = g[c] * rsqrtf(var + EPS_C);
    g_scale[layer][c] = sc;
    g_shift[layer][c] = bet[c] - mean*sc;
}

// -------- stage1 layer1: BN+ReLU + conv 32->32 --------
__global__ void k_conv_p1(const float* __restrict__ W) {
    __shared__ float a[NS1][33];
    __shared__ float Ws[32*32];
    __shared__ float ssum[32], ssq[32];
    int bm = blockIdx.x, tid = threadIdx.x, s = tid >> 5, c = tid & 31;
    for (int i = tid; i < 1024; i += 512) Ws[i] = W[i];
    if (tid < 32) { ssum[tid] = 0.f; ssq[tid] = 0.f; }
    a[s][c] = fmaxf(fmaf(g_bufA[bm*512 + tid], g_scale[0][c], g_shift[0][c]), 0.f);
    __syncthreads();
    float y = 0.f;
    #pragma unroll
    for (int k = 0; k < 32; k++) y = fmaf(a[s][k], Ws[k*32 + c], y);
    g_bufB[bm*512 + tid] = y;
    atomicAdd(&ssum[c], y);
    atomicAdd(&ssq[c], y*y);
    __syncthreads();
    if (tid < 32) { atomicAdd(&g_sum[1][tid], ssum[tid]); atomicAdd(&g_sq[1][tid], ssq[tid]); }
}

// -------- per-roi: BN+ReLU+maxpool fused into FC dot -> learned radius --------
__global__ void k_roi_fc(const float* __restrict__ roif, const float* __restrict__ fcw,
                         const float* __restrict__ fcb) {
    int br = blockIdx.x;              // b*RR + roi
    int b = br / RR, roi = br % RR;
    int tid = threadIdx.x;
    float acc = 0.f;
    for (int j = tid; j < 2048; j += 256) {
        int gp = j >> 5, c = j & 31;
        int base = (b*MM + roi*G3 + gp)*512 + c;
        float sc = g_scale[1][c], sh = g_shift[1][c];
        float mx = -1e30f;
        #pragma unroll
        for (int s = 0; s < NS1; s++)
            mx = fmaxf(mx, fmaxf(fmaf(g_bufB[base + s*32], sc, sh), 0.f));
        acc += mx * fcw[j];
    }
    for (int j = 2048 + tid; j < 2176; j += 256)
        acc += roif[br*128 + (j - 2048)] * fcw[j];
    __shared__ float red[256];
    red[tid] = acc;
    __syncthreads();
    for (int st = 128; st > 0; st >>= 1) {
        if (tid < st) red[tid] += red[tid + st];
        __syncthreads();
    }
    if (tid == 0) {
        float res = red[0] + fcb[0];
        g_rad[br] = fmaxf(res / DIV_COEF_C + RADIUS_C, MIN_R_C);
    }
}

// -------- stage2 layer0: gather + sigmoid weights + conv 35->64 --------
__global__ void k_conv_f0(const float* __restrict__ xyz, const float* __restrict__ feats,
                          const float* __restrict__ rois, const float* __restrict__ W,
                          const float* __restrict__ td) {
    __shared__ float xs[NS2][36];
    __shared__ float Ws[35*64];
    __shared__ float ssum[64], ssq[64];
    int bm = blockIdx.x, b = bm / MM, m = bm % MM;
    int tid = threadIdx.x;
    for (int i = tid; i < 35*64; i += 1024) Ws[i] = W[i];
    if (tid < 64) { ssum[tid] = 0.f; ssq[tid] = 0.f; }
    bool emp = g_empty[bm] != 0;
    float q0 = rois[bm*3+0], q1 = rois[bm*3+1], q2 = rois[bm*3+2];
    for (int i = tid; i < NS2*35; i += 1024) {
        int s = i / 35, k = i - s*35;
        int pidx = g_idx[bm*NS2 + s];
        float v;
        if (emp)       v = 0.f;
        else if (k < 3) v = xyz[((size_t)b*NN + pidx)*3 + k] - (k==0 ? q0 : (k==1 ? q1 : q2));
        else            v = feats[((size_t)b*NN + pidx)*CC + k - 3];
        xs[s][k] = v;
    }
    __syncthreads();
    if (tid < NS2) {
        int s = tid;
        float dx = xs[s][0], dy = xs[s][1], dz = xs[s][2];
        float dist = sqrtf(dx*dx + dy*dy + dz*dz);
        float r = g_rad[b*RR + m/G3];
        float t = td[0];                       // TEMPERATURE = 1.0
        g_w[bm*NS2 + s] = emp ? 0.f : 1.f / (1.f + expf(-(r - dist) / t));
    }
    int c = tid & 63, s0 = tid >> 6;           // s0 in 0..15, pairs with s0+16
    float y0 = 0.f, y1 = 0.f;
    #pragma unroll
    for (int k = 0; k < 35; k++) {
        float wv = Ws[k*64 + c];
        y0 = fmaf(xs[s0][k],    wv, y0);
        y1 = fmaf(xs[s0+16][k], wv, y1);
    }
    g_bufA[bm*2048 + s0*64 + c]      = y0;
    g_bufA[bm*2048 + (s0+16)*64 + c] = y1;
    atomicAdd(&ssum[c], y0 + y1);
    atomicAdd(&ssq[c], y0*y0 + y1*y1);
    __syncthreads();
    if (tid < 64) { atomicAdd(&g_sum[2][tid], ssum[tid]); atomicAdd(&g_sq[2][tid], ssq[tid]); }
}

// -------- stage2 layer1: BN+ReLU + conv 64->64 --------
__global__ void k_conv_f1(const float* __restrict__ W) {
    __shared__ float a[NS2][64];
    __shared__ float Ws[64*64];
    __shared__ float ssum[64], ssq[64];
    int bm = blockIdx.x, tid = threadIdx.x;
    for (int i = tid; i < 4096; i += 1024) Ws[i] = W[i];
    if (tid < 64) { ssum[tid] = 0.f; ssq[tid] = 0.f; }
    for (int i = tid; i < 2048; i += 1024) {
        int c = i & 63;
        a[i >> 6][c] = fmaxf(fmaf(g_bufA[bm*2048 + i], g_scale[2][c], g_shift[2][c]), 0.f);
    }
    __syncthreads();
    int c = tid & 63, s0 = tid >> 6;
    float y0 = 0.f, y1 = 0.f;
    #pragma unroll
    for (int k = 0; k < 64; k++) {
        float wv = Ws[k*64 + c];
        y0 = fmaf(a[s0][k],    wv, y0);
        y1 = fmaf(a[s0+16][k], wv, y1);
    }
    g_bufB[bm*2048 + s0*64 + c]      = y0;
    g_bufB[bm*2048 + (s0+16)*64 + c] = y1;
    atomicAdd(&ssum[c], y0 + y1);
    atomicAdd(&ssq[c], y0*y0 + y1*y1);
    __syncthreads();
    if (tid < 64) { atomicAdd(&g_sum[3][tid], ssum[tid]); atomicAdd(&g_sq[3][tid], ssq[tid]); }
}

// -------- final: BN+ReLU * w, max over samples -> output features --------
__global__ void k_out(float* __restrict__ out) {
    int bm = blockIdx.x, c = threadIdx.x;
    float sc = g_scale[3][c], sh = g_shift[3][c];
    float mx = -1e30f;
    #pragma unroll
    for (int s = 0; s < NS2; s++) {
        float v = fmaxf(fmaf(g_bufB[bm*2048 + s*64 + c], sc, sh), 0.f) * g_w[bm*NS2 + s];
        mx = fmaxf(mx, v);
    }
    out[BM*3 + bm*64 + c] = mx;
}

extern "C" void kernel_launch(void* const* d_in, const int* in_sizes, int n_in,
                              void* d_out, int out_size) {
    const float* xyz  = (const float*)d_in[0];
    const float* feats= (const float*)d_in[1];
    const float* rois = (const float*)d_in[2];
    const float* roif = (const float*)d_in[3];
    const float* td   = (const float*)d_in[4];
    const float* pw0  = (const float*)d_in[5];
    const float* pg0  = (const float*)d_in[6];
    const float* pb0  = (const float*)d_in[7];
    const float* pw1  = (const float*)d_in[8];
    const float* pg1  = (const float*)d_in[9];
    const float* pb1  = (const float*)d_in[10];
    const float* fw0  = (const float*)d_in[11];
    const float* fg0  = (const float*)d_in[12];
    const float* fb0  = (const float*)d_in[13];
    const float* fw1  = (const float*)d_in[14];
    const float* fg1  = (const float*)d_in[15];
    const float* fb1  = (const float*)d_in[16];
    const float* fcw  = (const float*)d_in[17];
    const float* fcb  = (const float*)d_in[18];
    float* out = (float*)d_out;

    // new_xyz output = rois reshaped
    cudaMemcpyAsync(out, rois, (size_t)BM*3*sizeof(float), cudaMemcpyDeviceToDevice, 0);

    k_zero<<<1, 64>>>();
    k_bq<<<BM/8, 256>>>(xyz, rois, NS1, 0);
    k_conv_p0<<<BM, 512>>>(xyz, feats, rois, pw0);
    k_fin<<<1, 64>>>(0, 32, (float)(BM*NS1), pg0, pb0);
    k_conv_p1<<<BM, 512>>>(pw1);
    k_fin<<<1, 64>>>(1, 32, (float)(BM*NS1), pg1, pb1);
    k_roi_fc<<<BB*RR, 256>>>(roif, fcw, fcb);
    k_bq<<<BM/8, 256>>>(xyz, rois, NS2, 1);
    k_conv_f0<<<BM, 1024>>>(xyz, feats, rois, fw0, td);
    k_fin<<<1, 64>>>(2, 64, (float)(BM*NS2), fg0, fb0);
    k_conv_f1<<<BM, 1024>>>(fw1);
    k_fin<<<1, 64>>>(3, 64, (float)(BM*NS2), fg1, fb1);
    k_out<<<BM, 64>>>(out);
}

// round 2
// speedup vs baseline: 1.6497x; 1.6497x over previous
#include <cuda_runtime.h>
#include <math.h>

#define BB 2
#define NN 8192
#define CC 32
#define RR 64
#define G3 64
#define MM (RR*G3)        /* 4096 queries per batch */
#define BM (BB*MM)        /* 8192 total queries */
#define NS1 16
#define NS2 32
#define RADIUS_C 0.8f
#define MIN_R_C 0.01f
#define DIV_COEF_C 10.0f
#define EPS_C 1e-5f
#define CNT1 ((float)(BM*NS1))
#define CNT2 ((float)(BM*NS2))

// -------- scratch (device globals; no allocation allowed) --------
__device__ float4 g_xyz4[BB*NN];      // points as float4 for 1-LDG loads
__device__ float g_bufA[BM*NS2*64];   // stage outputs (pre-BN)
__device__ float g_bufB[BM*NS2*64];
__device__ int   g_idx[BM*NS2];
__device__ unsigned char g_empty[BM];
__device__ float g_w[BM*NS2];
__device__ float g_rad[BB*RR];
__device__ float g_sum[4][64];
__device__ float g_sq[4][64];

// packed fp32x2 helpers (sm_100+ packed-fp32 pipe)
static __device__ __forceinline__ unsigned long long dup2(float a) {
    unsigned long long r;
    asm("mov.b64 %0, {%1, %1};" : "=l"(r) : "r"(__float_as_uint(a)));
    return r;
}
static __device__ __forceinline__ void fma2(unsigned long long &acc,
                                            unsigned long long a, unsigned long long b) {
    asm("fma.rn.f32x2 %0, %1, %2, %0;" : "+l"(acc) : "l"(a), "l"(b));
}
union U2 { unsigned long long u; float2 f; };

// -------- prep: xyz -> float4, zero BN stats (runs every graph replay) --------
__global__ void k_prep(const float* __restrict__ xyz) {
    int i = blockIdx.x * blockDim.x + threadIdx.x;
    if (i < BB*NN)
        g_xyz4[i] = make_float4(xyz[i*3], xyz[i*3+1], xyz[i*3+2], 0.f);
    if (blockIdx.x == 0 && threadIdx.x < 64) {
        #pragma unroll
        for (int j = 0; j < 4; j++) { g_sum[j][threadIdx.x] = 0.f; g_sq[j][threadIdx.x] = 0.f; }
    }
}

// -------- ball query: one warp per query, first-found ascending indices --------
__global__ void k_bq(const float* __restrict__ q, int nsample, int use_rad) {
    int wq   = (blockIdx.x * blockDim.x + threadIdx.x) >> 5;
    int lane = threadIdx.x & 31;
    if (wq >= BM) return;
    int b = wq / MM, m = wq % MM;
    float qx = q[wq*3+0], qy = q[wq*3+1], qz = q[wq*3+2];
    float r  = use_rad ? g_rad[b*RR + m/G3] : RADIUS_C;
    float r2 = r * r;
    const float4* xb = g_xyz4 + (size_t)b*NN;

    int cnt = 0, firstIdx = 0;
    bool have = false;
    for (int j0 = 0; j0 < NN; j0 += 32) {
        int i = j0 + lane;
        float4 p = xb[i];
        float dx = p.x - qx, dy = p.y - qy, dz = p.z - qz;
        float d2 = fmaf(dx,dx, fmaf(dy,dy, dz*dz));
        bool valid = d2 < r2;
        unsigned mask = __ballot_sync(0xffffffffu, valid);
        if (mask) {
            if (!have) { firstIdx = j0 + __ffs(mask) - 1; have = true; }
            int pos = cnt + __popc(mask & ((1u << lane) - 1u));
            if (valid && pos < nsample) g_idx[wq*NS2 + pos] = i;
            cnt += __popc(mask);
            if (cnt >= nsample) break;
        }
    }
    if (!have) {
        if (lane == 0) g_empty[wq] = 1;
        if (lane < nsample) g_idx[wq*NS2 + lane] = 0;
    } else {
        if (lane == 0) g_empty[wq] = 0;
        int cc = cnt < nsample ? cnt : nsample;
        if (lane >= cc && lane < nsample) g_idx[wq*NS2 + lane] = firstIdx;
    }
}

// -------- stage1 layer0: gather + conv 35->32 (4 bm/block, 8x4 reg tile) --------
__global__ void __launch_bounds__(64, 8)
k_conv_p0(const float* __restrict__ feats, const float* __restrict__ rois,
          const float* __restrict__ W) {
    __shared__ __align__(16) float At[35][68];
    __shared__ __align__(16) float Ws[35*32];
    __shared__ float ssum[32], ssq[32];
    int bmBase = blockIdx.x * 4;
    int tid = threadIdx.x;
    for (int i = tid; i < 35*32; i += 64) Ws[i] = W[i];
    if (tid < 32) { ssum[tid] = 0.f; ssq[tid] = 0.f; }
    {   // gather: one sample per thread (4 bm x 16 samples = 64)
        int bmL = tid >> 4, s = tid & 15;
        int bm = bmBase + bmL, b = bm / MM;
        bool emp = g_empty[bm] != 0;
        int pidx = g_idx[bm*NS2 + s];
        float4 p = g_xyz4[b*NN + pidx];
        float dx = emp ? 0.f : p.x - rois[bm*3+0];
        float dy = emp ? 0.f : p.y - rois[bm*3+1];
        float dz = emp ? 0.f : p.z - rois[bm*3+2];
        At[0][tid] = dx; At[1][tid] = dy; At[2][tid] = dz;
        const float4* f4 = (const float4*)(feats + ((size_t)b*NN + pidx)*CC);
        #pragma unroll
        for (int j = 0; j < 8; j++) {
            float4 v = emp ? make_float4(0,0,0,0) : f4[j];
            At[3+j*4+0][tid] = v.x; At[3+j*4+1][tid] = v.y;
            At[3+j*4+2][tid] = v.z; At[3+j*4+3][tid] = v.w;
        }
    }
    __syncthreads();
    int m0 = (tid >> 3) * 8, c0 = (tid & 7) * 4;
    unsigned long long acc[8][2] = {};
    for (int k = 0; k < 35; k++) {
        float4 a01 = *(const float4*)&At[k][m0];
        float4 a23 = *(const float4*)&At[k][m0+4];
        unsigned long long w0 = *(const unsigned long long*)&Ws[k*32 + c0];
        unsigned long long w1 = *(const unsigned long long*)&Ws[k*32 + c0 + 2];
        unsigned long long a2[8] = { dup2(a01.x), dup2(a01.y), dup2(a01.z), dup2(a01.w),
                                     dup2(a23.x), dup2(a23.y), dup2(a23.z), dup2(a23.w) };
        #pragma unroll
        for (int m = 0; m < 8; m++) { fma2(acc[m][0], a2[m], w0); fma2(acc[m][1], a2[m], w1); }
    }
    float ps[4] = {0,0,0,0}, pq[4] = {0,0,0,0};
    #pragma unroll
    for (int m = 0; m < 8; m++) {
        int mm = m0 + m, bm = bmBase + (mm >> 4), s = mm & 15;
        U2 u0, u1; u0.u = acc[m][0]; u1.u = acc[m][1];
        float4 y = make_float4(u0.f.x, u0.f.y, u1.f.x, u1.f.y);
        *(float4*)&g_bufA[bm*512 + s*32 + c0] = y;
        ps[0] += y.x; ps[1] += y.y; ps[2] += y.z; ps[3] += y.w;
        pq[0] += y.x*y.x; pq[1] += y.y*y.y; pq[2] += y.z*y.z; pq[3] += y.w*y.w;
    }
    #pragma unroll
    for (int n = 0; n < 4; n++) { atomicAdd(&ssum[c0+n], ps[n]); atomicAdd(&ssq[c0+n], pq[n]); }
    __syncthreads();
    if (tid < 32) { atomicAdd(&g_sum[0][tid], ssum[tid]); atomicAdd(&g_sq[0][tid], ssq[tid]); }
}

// -------- stage1 layer1: BN0+ReLU + conv 32->32 --------
__global__ void __launch_bounds__(64, 8)
k_conv_p1(const float* __restrict__ W, const float* __restrict__ gam, const float* __restrict__ bet) {
    __shared__ __align__(16) float At[32][68];
    __shared__ __align__(16) float Ws[32*32];
    __shared__ float ssum[32], ssq[32], s_sc[32], s_sh[32];
    int bmBase = blockIdx.x * 4;
    int tid = threadIdx.x;
    for (int i = tid; i < 32*32; i += 64) Ws[i] = W[i];
    if (tid < 32) {
        ssum[tid] = 0.f; ssq[tid] = 0.f;
        float mean = g_sum[0][tid] * (1.f/CNT1);
        float var  = g_sq[0][tid] * (1.f/CNT1) - mean*mean;
        float sc   = gam[tid] * rsqrtf(var + EPS_C);
        s_sc[tid] = sc; s_sh[tid] = bet[tid] - mean*sc;
    }
    __syncthreads();
    for (int i = tid; i < 2048; i += 64) {
        int c = i & 31, m = i >> 5;
        At[c][m] = fmaxf(fmaf(g_bufA[bmBase*512 + i], s_sc[c], s_sh[c]), 0.f);
    }
    __syncthreads();
    int m0 = (tid >> 3) * 8, c0 = (tid & 7) * 4;
    unsigned long long acc[8][2] = {};
    for (int k = 0; k < 32; k++) {
        float4 a01 = *(const float4*)&At[k][m0];
        float4 a23 = *(const float4*)&At[k][m0+4];
        unsigned long long w0 = *(const unsigned long long*)&Ws[k*32 + c0];
        unsigned long long w1 = *(const unsigned long long*)&Ws[k*32 + c0 + 2];
        unsigned long long a2[8] = { dup2(a01.x), dup2(a01.y), dup2(a01.z), dup2(a01.w),
                                     dup2(a23.x), dup2(a23.y), dup2(a23.z), dup2(a23.w) };
        #pragma unroll
        for (int m = 0; m < 8; m++) { fma2(acc[m][0], a2[m], w0); fma2(acc[m][1], a2[m], w1); }
    }
    float ps[4] = {0,0,0,0}, pq[4] = {0,0,0,0};
    #pragma unroll
    for (int m = 0; m < 8; m++) {
        int mm = m0 + m, bm = bmBase + (mm >> 4), s = mm & 15;
        U2 u0, u1; u0.u = acc[m][0]; u1.u = acc[m][1];
        float4 y = make_float4(u0.f.x, u0.f.y, u1.f.x, u1.f.y);
        *(float4*)&g_bufB[bm*512 + s*32 + c0] = y;
        ps[0] += y.x; ps[1] += y.y; ps[2] += y.z; ps[3] += y.w;
        pq[0] += y.x*y.x; pq[1] += y.y*y.y; pq[2] += y.z*y.z; pq[3] += y.w*y.w;
    }
    #pragma unroll
    for (int n = 0; n < 4; n++) { atomicAdd(&ssum[c0+n], ps[n]); atomicAdd(&ssq[c0+n], pq[n]); }
    __syncthreads();
    if (tid < 32) { atomicAdd(&g_sum[1][tid], ssum[tid]); atomicAdd(&g_sq[1][tid], ssq[tid]); }
}

// -------- per-roi: BN1+ReLU+maxpool fused into FC dot -> learned radius --------
__global__ void k_roi_fc(const float* __restrict__ roif, const float* __restrict__ fcw,
                         const float* __restrict__ fcb,
                         const float* __restrict__ gam, const float* __restrict__ bet) {
    __shared__ float s_sc[32], s_sh[32];
    __shared__ float red[256];
    int br = blockIdx.x, b = br / RR, roi = br % RR;
    int tid = threadIdx.x;
    if (tid < 32) {
        float mean = g_sum[1][tid] * (1.f/CNT1);
        float var  = g_sq[1][tid] * (1.f/CNT1) - mean*mean;
        float sc   = gam[tid] * rsqrtf(var + EPS_C);
        s_sc[tid] = sc; s_sh[tid] = bet[tid] - mean*sc;
    }
    __syncthreads();
    float acc = 0.f;
    for (int j = tid; j < 2048; j += 256) {
        int gp = j >> 5, c = j & 31;
        int base = (b*MM + roi*G3 + gp)*512 + c;
        float sc = s_sc[c], sh = s_sh[c];
        float mx = -1e30f;
        #pragma unroll
        for (int s = 0; s < NS1; s++)
            mx = fmaxf(mx, fmaxf(fmaf(g_bufB[base + s*32], sc, sh), 0.f));
        acc += mx * fcw[j];
    }
    for (int j = 2048 + tid; j < 2176; j += 256)
        acc += roif[br*128 + (j - 2048)] * fcw[j];
    red[tid] = acc;
    __syncthreads();
    for (int st = 128; st > 0; st >>= 1) {
        if (tid < st) red[tid] += red[tid + st];
        __syncthreads();
    }
    if (tid == 0)
        g_rad[br] = fmaxf((red[0] + fcb[0]) / DIV_COEF_C + RADIUS_C, MIN_R_C);
}

// -------- stage2 layer0: gather + sigmoid w + conv 35->64 (2 bm/block, 8x8 tile) ----
__global__ void __launch_bounds__(64, 8)
k_conv_f0(const float* __restrict__ feats, const float* __restrict__ rois,
          const float* __restrict__ W, const float* __restrict__ td) {
    __shared__ __align__(16) float At[35][68];
    __shared__ __align__(16) float Ws[35*64];
    __shared__ float ssum[64], ssq[64];
    int bmBase = blockIdx.x * 2;
    int tid = threadIdx.x;
    for (int i = tid; i < 35*64; i += 64) Ws[i] = W[i];
    if (tid < 64) { ssum[tid] = 0.f; ssq[tid] = 0.f; }
    {   // gather: one sample per thread (2 bm x 32 samples = 64)
        int bmL = tid >> 5, s = tid & 31;
        int bm = bmBase + bmL, b = bm / MM;
        bool emp = g_empty[bm] != 0;
        int pidx = g_idx[bm*NS2 + s];
        float4 p = g_xyz4[b*NN + pidx];
        float dx = emp ? 0.f : p.x - rois[bm*3+0];
        float dy = emp ? 0.f : p.y - rois[bm*3+1];
        float dz = emp ? 0.f : p.z - rois[bm*3+2];
        At[0][tid] = dx; At[1][tid] = dy; At[2][tid] = dz;
        const float4* f4 = (const float4*)(feats + ((size_t)b*NN + pidx)*CC);
        #pragma unroll
        for (int j = 0; j < 8; j++) {
            float4 v = emp ? make_float4(0,0,0,0) : f4[j];
            At[3+j*4+0][tid] = v.x; At[3+j*4+1][tid] = v.y;
            At[3+j*4+2][tid] = v.z; At[3+j*4+3][tid] = v.w;
        }
        float dist = sqrtf(dx*dx + dy*dy + dz*dz);
        float r = g_rad[b*RR + ((bm % MM) >> 6)];
        g_w[bm*NS2 + s] = emp ? 0.f : 1.f / (1.f + expf(-(r - dist) / td[0]));
    }
    __syncthreads();
    int m0 = (tid >> 3) * 8, c0 = (tid & 7) * 8;
    unsigned long long acc[8][4] = {};
    for (int k = 0; k < 35; k++) {
        float4 a01 = *(const float4*)&At[k][m0];
        float4 a23 = *(const float4*)&At[k][m0+4];
        const unsigned long long* wp = (const unsigned long long*)&Ws[k*64 + c0];
        unsigned long long w0 = wp[0], w1 = wp[1], w2 = wp[2], w3 = wp[3];
        unsigned long long a2[8] = { dup2(a01.x), dup2(a01.y), dup2(a01.z), dup2(a01.w),
                                     dup2(a23.x), dup2(a23.y), dup2(a23.z), dup2(a23.w) };
        #pragma unroll
        for (int m = 0; m < 8; m++) {
            fma2(acc[m][0], a2[m], w0); fma2(acc[m][1], a2[m], w1);
            fma2(acc[m][2], a2[m], w2); fma2(acc[m][3], a2[m], w3);
        }
    }
    float ps[8] = {0,0,0,0,0,0,0,0}, pq[8] = {0,0,0,0,0,0,0,0};
    #pragma unroll
    for (int m = 0; m < 8; m++) {
        int mm = m0 + m, bm = bmBase + (mm >> 5), s = mm & 31;
        U2 u[4]; float y[8];
        #pragma unroll
        for (int n = 0; n < 4; n++) { u[n].u = acc[m][n]; y[2*n] = u[n].f.x; y[2*n+1] = u[n].f.y; }
        *(float4*)&g_bufA[bm*2048 + s*64 + c0]     = make_float4(y[0], y[1], y[2], y[3]);
        *(float4*)&g_bufA[bm*2048 + s*64 + c0 + 4] = make_float4(y[4], y[5], y[6], y[7]);
        #pragma unroll
        for (int n = 0; n < 8; n++) { ps[n] += y[n]; pq[n] += y[n]*y[n]; }
    }
    #pragma unroll
    for (int n = 0; n < 8; n++) { atomicAdd(&ssum[c0+n], ps[n]); atomicAdd(&ssq[c0+n], pq[n]); }
    __syncthreads();
    if (tid < 64) { atomicAdd(&g_sum[2][tid], ssum[tid]); atomicAdd(&g_sq[2][tid], ssq[tid]); }
}

// -------- stage2 layer1: BN2+ReLU + conv 64->64 (2 bm/block, 8x8 tile) --------
__global__ void __launch_bounds__(64, 8)
k_conv_f1(const float* __restrict__ W, const float* __restrict__ gam, const float* __restrict__ bet) {
    __shared__ __align__(16) float At[64][68];
    __shared__ __align__(16) float Ws[64*64];
    __shared__ float ssum[64], ssq[64], s_sc[64], s_sh[64];
    int bmBase = blockIdx.x * 2;
    int tid = threadIdx.x;
    for (int i = tid; i < 64*64; i += 64) Ws[i] = W[i];
    if (tid < 64) {
        ssum[tid] = 0.f; ssq[tid] = 0.f;
        float mean = g_sum[2][tid] * (1.f/CNT2);
        float var  = g_sq[2][tid] * (1.f/CNT2) - mean*mean;
        float sc   = gam[tid] * rsqrtf(var + EPS_C);
        s_sc[tid] = sc; s_sh[tid] = bet[tid] - mean*sc;
    }
    __syncthreads();
    for (int i = tid; i < 4096; i += 64) {
        int c = i & 63, m = i >> 6;
        At[c][m] = fmaxf(fmaf(g_bufA[bmBase*2048 + i], s_sc[c], s_sh[c]), 0.f);
    }
    __syncthreads();
    int m0 = (tid >> 3) * 8, c0 = (tid & 7) * 8;
    unsigned long long acc[8][4] = {};
    for (int k = 0; k < 64; k++) {
        float4 a01 = *(const float4*)&At[k][m0];
        float4 a23 = *(const float4*)&At[k][m0+4];
        const unsigned long long* wp = (const unsigned long long*)&Ws[k*64 + c0];
        unsigned long long w0 = wp[0], w1 = wp[1], w2 = wp[2], w3 = wp[3];
        unsigned long long a2[8] = { dup2(a01.x), dup2(a01.y), dup2(a01.z), dup2(a01.w),
                                     dup2(a23.x), dup2(a23.y), dup2(a23.z), dup2(a23.w) };
        #pragma unroll
        for (int m = 0; m < 8; m++) {
            fma2(acc[m][0], a2[m], w0); fma2(acc[m][1], a2[m], w1);
            fma2(acc[m][2], a2[m], w2); fma2(acc[m][3], a2[m], w3);
        }
    }
    float ps[8] = {0,0,0,0,0,0,0,0}, pq[8] = {0,0,0,0,0,0,0,0};
    #pragma unroll
    for (int m = 0; m < 8; m++) {
        int mm = m0 + m, bm = bmBase + (mm >> 5), s = mm & 31;
        U2 u[4]; float y[8];
        #pragma unroll
        for (int n = 0; n < 4; n++) { u[n].u = acc[m][n]; y[2*n] = u[n].f.x; y[2*n+1] = u[n].f.y; }
        *(float4*)&g_bufB[bm*2048 + s*64 + c0]     = make_float4(y[0], y[1], y[2], y[3]);
        *(float4*)&g_bufB[bm*2048 + s*64 + c0 + 4] = make_float4(y[4], y[5], y[6], y[7]);
        #pragma unroll
        for (int n = 0; n < 8; n++) { ps[n] += y[n]; pq[n] += y[n]*y[n]; }
    }
    #pragma unroll
    for (int n = 0; n < 8; n++) { atomicAdd(&ssum[c0+n], ps[n]); atomicAdd(&ssq[c0+n], pq[n]); }
    __syncthreads();
    if (tid < 64) { atomicAdd(&g_sum[3][tid], ssum[tid]); atomicAdd(&g_sq[3][tid], ssq[tid]); }
}

// -------- final: BN3+ReLU * w, max over samples --------
__global__ void k_out(float* __restrict__ out, const float* __restrict__ gam,
                      const float* __restrict__ bet) {
    __shared__ float s_sc[64], s_sh[64];
    int tid = threadIdx.x;
    if (tid < 64) {
        float mean = g_sum[3][tid] * (1.f/CNT2);
        float var  = g_sq[3][tid] * (1.f/CNT2) - mean*mean;
        float sc   = gam[tid] * rsqrtf(var + EPS_C);
        s_sc[tid] = sc; s_sh[tid] = bet[tid] - mean*sc;
    }
    __syncthreads();
    int c = tid & 63, bmL = tid >> 6;
    int bm = blockIdx.x * 4 + bmL;
    float sc = s_sc[c], sh = s_sh[c];
    float mx = -1e30f;
    #pragma unroll
    for (int s = 0; s < NS2; s++) {
        float v = fmaxf(fmaf(g_bufB[bm*2048 + s*64 + c], sc, sh), 0.f) * g_w[bm*NS2 + s];
        mx = fmaxf(mx, v);
    }
    out[BM*3 + bm*64 + c] = mx;
}

extern "C" void kernel_launch(void* const* d_in, const int* in_sizes, int n_in,
                              void* d_out, int out_size) {
    const float* xyz  = (const float*)d_in[0];
    const float* feats= (const float*)d_in[1];
    const float* rois = (const float*)d_in[2];
    const float* roif = (const float*)d_in[3];
    const float* td   = (const float*)d_in[4];
    const float* pw0  = (const float*)d_in[5];
    const float* pg0  = (const float*)d_in[6];
    const float* pb0  = (const float*)d_in[7];
    const float* pw1  = (const float*)d_in[8];
    const float* pg1  = (const float*)d_in[9];
    const float* pb1  = (const float*)d_in[10];
    const float* fw0  = (const float*)d_in[11];
    const float* fg0  = (const float*)d_in[12];
    const float* fb0  = (const float*)d_in[13];
    const float* fw1  = (const float*)d_in[14];
    const float* fg1  = (const float*)d_in[15];
    const float* fb1  = (const float*)d_in[16];
    const float* fcw  = (const float*)d_in[17];
    const float* fcb  = (const float*)d_in[18];
    float* out = (float*)d_out;

    cudaMemcpyAsync(out, rois, (size_t)BM*3*sizeof(float), cudaMemcpyDeviceToDevice, 0);

    k_prep<<<32, 512>>>(xyz);
    k_bq<<<BM/8, 256>>>(rois, NS1, 0);
    k_conv_p0<<<BM/4, 64>>>(feats, rois, pw0);
    k_conv_p1<<<BM/4, 64>>>(pw1, pg0, pb0);
    k_roi_fc<<<BB*RR, 256>>>(roif, fcw, fcb, pg1, pb1);
    k_bq<<<BM/8, 256>>>(rois, NS2, 1);
    k_conv_f0<<<BM/2, 64>>>(feats, rois, fw0, td);
    k_conv_f1<<<BM/2, 64>>>(fw1, fg0, fb0);
    k_out<<<BM/4, 256>>>(out, fg1, fb1);
}

// round 5
// speedup vs baseline: 1.7174x; 1.0410x over previous
#include <cuda_runtime.h>
#include <math.h>

#define BB 2
#define NN 8192
#define CC 32
#define RR 64
#define G3 64
#define MM (RR*G3)
#define BM (BB*MM)
#define NS1 16
#define NS2 32
#define RADIUS_C 0.8f
#define MIN_R_C 0.01f
#define DIV_COEF_C 10.0f
#define EPS_C 1e-5f
#define CNT1 ((float)(BM*NS1))
#define CNT2 ((float)(BM*NS2))

// spatial hash grid: cell size 0.8, scene 10x10x4
#define CSINV 1.25f
#define NX 13
#define NY 13
#define NZ 5
#define NCELL (NX*NY*NZ)      /* 845 per batch */

// -------- scratch --------
__device__ float4 g_xyz4[BB*NN];
__device__ float4 g_pts4[BB*NN];      // cell-sorted points, .w = original index (int bits)
__device__ int   g_pcell[BB*NN];
__device__ int   g_cellStart[2*NCELL+1];
__device__ int   g_cur[2*NCELL];
__device__ float g_bufA[BM*NS2*64];
__device__ float g_bufB[BM*NS2*64];
__device__ int   g_idx[BM*NS2];
__device__ unsigned char g_empty[BM];
__device__ float g_w[BM*NS2];
__device__ float g_rad[BB*RR];
__device__ float g_sum[4][64];
__device__ float g_sq[4][64];

static __device__ __forceinline__ unsigned long long dup2(float a) {
    unsigned long long r;
    asm("mov.b64 %0, {%1, %1};" : "=l"(r) : "r"(__float_as_uint(a)));
    return r;
}
static __device__ __forceinline__ void fma2(unsigned long long &acc,
                                            unsigned long long a, unsigned long long b) {
    asm("fma.rn.f32x2 %0, %1, %2, %0;" : "+l"(acc) : "l"(a), "l"(b));
}
union U2 { unsigned long long u; float2 f; };

// -------- prep: xyz->float4, cell ids, zero BN stats --------
__global__ void k_prep(const float* __restrict__ xyz) {
    int i = blockIdx.x * blockDim.x + threadIdx.x;
    if (i < BB*NN) {
        float x = xyz[i*3], y = xyz[i*3+1], z = xyz[i*3+2];
        g_xyz4[i] = make_float4(x, y, z, 0.f);
        int cx = min(NX-1, max(0, (int)(x*CSINV)));
        int cy = min(NY-1, max(0, (int)(y*CSINV)));
        int cz = min(NZ-1, max(0, (int)(z*CSINV)));
        g_pcell[i] = (i >> 13)*NCELL + (cz*NY + cy)*NX + cx;
    }
    if (blockIdx.x == 0 && threadIdx.x < 64) {
        #pragma unroll
        for (int j = 0; j < 4; j++) { g_sum[j][threadIdx.x] = 0.f; g_sq[j][threadIdx.x] = 0.f; }
    }
}

// -------- grid build: count + prefix (single block) --------
__global__ void k_grid() {
    __shared__ int cntS[2*NCELL];
    __shared__ int bufS[2*NCELL];
    int tid = threadIdx.x;
    for (int i = tid; i < 2*NCELL; i += 1024) cntS[i] = 0;
    __syncthreads();
    for (int i = tid; i < BB*NN; i += 1024) atomicAdd(&cntS[g_pcell[i]], 1);
    __syncthreads();
    int *src = cntS, *dst = bufS;
    for (int off = 1; off < 2*NCELL; off <<= 1) {
        for (int i = tid; i < 2*NCELL; i += 1024)
            dst[i] = src[i] + (i >= off ? src[i-off] : 0);
        __syncthreads();
        int *t = src; src = dst; dst = t;
    }
    for (int i = tid; i < 2*NCELL; i += 1024) {
        g_cellStart[i+1] = src[i];
        g_cur[i] = (i == 0) ? 0 : src[i-1];
    }
    if (tid == 0) g_cellStart[0] = 0;
}

// -------- scatter points into cell order --------
__global__ void k_scatter() {
    int i = blockIdx.x * blockDim.x + threadIdx.x;
    if (i >= BB*NN) return;
    int cell = g_pcell[i];
    int slot = atomicAdd(&g_cur[cell], 1);
    float4 p = g_xyz4[i];
    p.w = __int_as_float(i & (NN-1));
    g_pts4[slot] = p;
}

// -------- ball query via grid + per-warp bitmap (exact ascending-index order) ----
__global__ void __launch_bounds__(256)
k_bq(const float* __restrict__ q, int nsample, int use_rad) {
    __shared__ unsigned bmS[8][256];
    const unsigned F = 0xffffffffu;
    int w = threadIdx.x >> 5, lane = threadIdx.x & 31;
    int wq = blockIdx.x * 8 + w;
    int b = wq >> 12, m = wq & (MM-1);
    float qx = q[wq*3+0], qy = q[wq*3+1], qz = q[wq*3+2];
    float r  = use_rad ? g_rad[b*RR + (m >> 6)] : RADIUS_C;
    float r2 = r * r;

    for (int j = lane; j < 256; j += 32) bmS[w][j] = 0;
    __syncwarp();

    float rm = r + 1e-4f;
    int cx0 = max(0,    (int)floorf((qx-rm)*CSINV));
    int cx1 = min(NX-1, (int)floorf((qx+rm)*CSINV));
    int cy0 = max(0,    (int)floorf((qy-rm)*CSINV));
    int cy1 = min(NY-1, (int)floorf((qy+rm)*CSINV));
    int cz0 = max(0,    (int)floorf((qz-rm)*CSINV));
    int cz1 = min(NZ-1, (int)floorf((qz+rm)*CSINV));

    for (int cz = cz0; cz <= cz1; cz++)
      for (int cy = cy0; cy <= cy1; cy++)
        for (int cx = cx0; cx <= cx1; cx++) {
            int cell = b*NCELL + (cz*NY + cy)*NX + cx;
            int s0 = g_cellStart[cell], s1 = g_cellStart[cell+1];
            for (int j = s0 + lane; j < s1; j += 32) {
                float4 p = g_pts4[j];
                float dx = p.x - qx, dy = p.y - qy, dz = p.z - qz;
                float d2 = fmaf(dx,dx, fmaf(dy,dy, dz*dz));
                if (d2 < r2) {
                    int idx = __float_as_int(p.w);
                    atomicOr(&bmS[w][idx >> 5], 1u << (idx & 31));
                }
            }
        }
    __syncwarp();

    // extract first nsample set bits in ascending order
    int total = 0, firstIdx = 0;
    bool have = false;
    #pragma unroll
    for (int ch = 0; ch < 8; ch++) {
        unsigned wd = bmS[w][ch*32 + lane];
        int c = __popc(wd);
        int inc = c;
        #pragma unroll
        for (int off = 1; off < 32; off <<= 1) {
            int v = __shfl_up_sync(F, inc, off);
            if (lane >= off) inc += v;
        }
        int pre = inc - c;
        unsigned any = __ballot_sync(F, wd != 0);
        if (!have && any) {
            int src = __ffs(any) - 1;
            unsigned fw = __shfl_sync(F, wd, src);
            firstIdx = (ch*32 + src)*32 + (__ffs(fw) - 1);
            have = true;
        }
        int warpCnt = __shfl_sync(F, inc, 31);
        int base = total + pre;
        while (wd && base < nsample) {
            int bp = __ffs(wd) - 1; wd &= wd - 1;
            g_idx[wq*NS2 + base] = (ch*32 + lane)*32 + bp;
            base++;
        }
        total += warpCnt;
        if (total >= nsample) break;
    }
    int cc = total < nsample ? total : nsample;
    if (!have) {
        if (lane == 0) g_empty[wq] = 1;
        if (lane < nsample) g_idx[wq*NS2 + lane] = 0;
    } else {
        if (lane == 0) g_empty[wq] = 0;
        if (lane >= cc && lane < nsample) g_idx[wq*NS2 + lane] = firstIdx;
    }
}

// -------- stage1 layer0: gather + conv 35->32 (8 bm/block, 128 thr, 8x4 tile) ----
__global__ void __launch_bounds__(128, 8)
k_conv_p0(const float* __restrict__ feats, const float* __restrict__ rois,
          const float* __restrict__ W) {
    __shared__ __align__(16) float At[35][132];
    __shared__ __align__(16) float Ws[35*32];
    __shared__ float ssum[32], ssq[32];
    int bmBase = blockIdx.x * 8;
    int tid = threadIdx.x;
    for (int i = tid; i < 35*32; i += 128) Ws[i] = W[i];
    if (tid < 32) { ssum[tid] = 0.f; ssq[tid] = 0.f; }
    {   // one sample per thread: 8 bm x 16 s = 128
        int bm = bmBase + (tid >> 4), b = bm / MM;
        int s = tid & 15;
        bool emp = g_empty[bm] != 0;
        int pidx = g_idx[bm*NS2 + s];
        float4 p = g_xyz4[b*NN + pidx];
        At[0][tid] = emp ? 0.f : p.x - rois[bm*3+0];
        At[1][tid] = emp ? 0.f : p.y - rois[bm*3+1];
        At[2][tid] = emp ? 0.f : p.z - rois[bm*3+2];
        const float4* f4 = (const float4*)(feats + ((size_t)b*NN + pidx)*CC);
        #pragma unroll
        for (int j = 0; j < 8; j++) {
            float4 v = emp ? make_float4(0,0,0,0) : f4[j];
            At[3+j*4+0][tid] = v.x; At[3+j*4+1][tid] = v.y;
            At[3+j*4+2][tid] = v.z; At[3+j*4+3][tid] = v.w;
        }
    }
    __syncthreads();
    int m0 = (tid >> 3) * 8, c0 = (tid & 7) * 4;
    unsigned long long acc[8][2] = {};
    for (int k = 0; k < 35; k++) {
        float4 a01 = *(const float4*)&At[k][m0];
        float4 a23 = *(const float4*)&At[k][m0+4];
        unsigned long long w0 = *(const unsigned long long*)&Ws[k*32 + c0];
        unsigned long long w1 = *(const unsigned long long*)&Ws[k*32 + c0 + 2];
        float av[8] = { a01.x, a01.y, a01.z, a01.w, a23.x, a23.y, a23.z, a23.w };
        #pragma unroll
        for (int m = 0; m < 8; m++) {
            unsigned long long am = dup2(av[m]);
            fma2(acc[m][0], am, w0); fma2(acc[m][1], am, w1);
        }
    }
    float ps[4] = {0,0,0,0}, pq[4] = {0,0,0,0};
    #pragma unroll
    for (int m = 0; m < 8; m++) {
        int mm = m0 + m, bm = bmBase + (mm >> 4), s = mm & 15;
        U2 u0, u1; u0.u = acc[m][0]; u1.u = acc[m][1];
        float4 y = make_float4(u0.f.x, u0.f.y, u1.f.x, u1.f.y);
        *(float4*)&g_bufA[bm*512 + s*32 + c0] = y;
        ps[0] += y.x; ps[1] += y.y; ps[2] += y.z; ps[3] += y.w;
        pq[0] += y.x*y.x; pq[1] += y.y*y.y; pq[2] += y.z*y.z; pq[3] += y.w*y.w;
    }
    #pragma unroll
    for (int n = 0; n < 4; n++) { atomicAdd(&ssum[c0+n], ps[n]); atomicAdd(&ssq[c0+n], pq[n]); }
    __syncthreads();
    if (tid < 32) { atomicAdd(&g_sum[0][tid], ssum[tid]); atomicAdd(&g_sq[0][tid], ssq[tid]); }
}

// -------- stage1 layer1: BN0+ReLU + conv 32->32 --------
__global__ void __launch_bounds__(128, 8)
k_conv_p1(const float* __restrict__ W, const float* __restrict__ gam, const float* __restrict__ bet) {
    __shared__ __align__(16) float At[32][132];
    __shared__ __align__(16) float Ws[32*32];
    __shared__ float ssum[32], ssq[32], s_sc[32], s_sh[32];
    int bmBase = blockIdx.x * 8;
    int tid = threadIdx.x;
    for (int i = tid; i < 1024; i += 128) Ws[i] = W[i];
    if (tid < 32) {
        ssum[tid] = 0.f; ssq[tid] = 0.f;
        float mean = g_sum[0][tid] * (1.f/CNT1);
        float var  = g_sq[0][tid] * (1.f/CNT1) - mean*mean;
        float sc   = gam[tid] * rsqrtf(var + EPS_C);
        s_sc[tid] = sc; s_sh[tid] = bet[tid] - mean*sc;
    }
    __syncthreads();
    for (int i = tid; i < 4096; i += 128) {
        int c = i & 31, m = i >> 5;
        At[c][m] = fmaxf(fmaf(g_bufA[bmBase*512 + i], s_sc[c], s_sh[c]), 0.f);
    }
    __syncthreads();
    int m0 = (tid >> 3) * 8, c0 = (tid & 7) * 4;
    unsigned long long acc[8][2] = {};
    for (int k = 0; k < 32; k++) {
        float4 a01 = *(const float4*)&At[k][m0];
        float4 a23 = *(const float4*)&At[k][m0+4];
        unsigned long long w0 = *(const unsigned long long*)&Ws[k*32 + c0];
        unsigned long long w1 = *(const unsigned long long*)&Ws[k*32 + c0 + 2];
        float av[8] = { a01.x, a01.y, a01.z, a01.w, a23.x, a23.y, a23.z, a23.w };
        #pragma unroll
        for (int m = 0; m < 8; m++) {
            unsigned long long am = dup2(av[m]);
            fma2(acc[m][0], am, w0); fma2(acc[m][1], am, w1);
        }
    }
    float ps[4] = {0,0,0,0}, pq[4] = {0,0,0,0};
    #pragma unroll
    for (int m = 0; m < 8; m++) {
        int mm = m0 + m, bm = bmBase + (mm >> 4), s = mm & 15;
        U2 u0, u1; u0.u = acc[m][0]; u1.u = acc[m][1];
        float4 y = make_float4(u0.f.x, u0.f.y, u1.f.x, u1.f.y);
        *(float4*)&g_bufB[bm*512 + s*32 + c0] = y;
        ps[0] += y.x; ps[1] += y.y; ps[2] += y.z; ps[3] += y.w;
        pq[0] += y.x*y.x; pq[1] += y.y*y.y; pq[2] += y.z*y.z; pq[3] += y.w*y.w;
    }
    #pragma unroll
    for (int n = 0; n < 4; n++) { atomicAdd(&ssum[c0+n], ps[n]); atomicAdd(&ssq[c0+n], pq[n]); }
    __syncthreads();
    if (tid < 32) { atomicAdd(&g_sum[1][tid], ssum[tid]); atomicAdd(&g_sq[1][tid], ssq[tid]); }
}

// -------- per-roi FC -> learned radius --------
__global__ void k_roi_fc(const float* __restrict__ roif, const float* __restrict__ fcw,
                         const float* __restrict__ fcb,
                         const float* __restrict__ gam, const float* __restrict__ bet) {
    __shared__ float s_sc[32], s_sh[32];
    __shared__ float red[256];
    int br = blockIdx.x, b = br / RR, roi = br % RR;
    int tid = threadIdx.x;
    if (tid < 32) {
        float mean = g_sum[1][tid] * (1.f/CNT1);
        float var  = g_sq[1][tid] * (1.f/CNT1) - mean*mean;
        float sc   = gam[tid] * rsqrtf(var + EPS_C);
        s_sc[tid] = sc; s_sh[tid] = bet[tid] - mean*sc;
    }
    __syncthreads();
    float acc = 0.f;
    for (int j = tid; j < 2048; j += 256) {
        int gp = j >> 5, c = j & 31;
        int base = (b*MM + roi*G3 + gp)*512 + c;
        float sc = s_sc[c], sh = s_sh[c];
        float mx = -1e30f;
        #pragma unroll
        for (int s = 0; s < NS1; s++)
            mx = fmaxf(mx, fmaxf(fmaf(g_bufB[base + s*32], sc, sh), 0.f));
        acc += mx * fcw[j];
    }
    for (int j = 2048 + tid; j < 2176; j += 256)
        acc += roif[br*128 + (j - 2048)] * fcw[j];
    red[tid] = acc;
    __syncthreads();
    for (int st = 128; st > 0; st >>= 1) {
        if (tid < st) red[tid] += red[tid + st];
        __syncthreads();
    }
    if (tid == 0)
        g_rad[br] = fmaxf((red[0] + fcb[0]) / DIV_COEF_C + RADIUS_C, MIN_R_C);
}

// -------- stage2 layer0: gather + sigmoid w + conv 35->64 (2 bm/block, 4x8 tile) --
__global__ void __launch_bounds__(128, 7)
k_conv_f0(const float* __restrict__ feats, const float* __restrict__ rois,
          const float* __restrict__ W, const float* __restrict__ td) {
    __shared__ __align__(16) float At[35][68];
    __shared__ __align__(16) float Ws[35*64];
    __shared__ float ssum[64], ssq[64];
    int bmBase = blockIdx.x * 2;
    int tid = threadIdx.x;
    for (int i = tid; i < 35*64; i += 128) Ws[i] = W[i];
    if (tid < 64) { ssum[tid] = 0.f; ssq[tid] = 0.f; }
    if (tid < 64) {   // one sample per thread: 2 bm x 32 s = 64
        int bm = bmBase + (tid >> 5), b = bm / MM;
        int s = tid & 31;
        bool emp = g_empty[bm] != 0;
        int pidx = g_idx[bm*NS2 + s];
        float4 p = g_xyz4[b*NN + pidx];
        float dx = emp ? 0.f : p.x - rois[bm*3+0];
        float dy = emp ? 0.f : p.y - rois[bm*3+1];
        float dz = emp ? 0.f : p.z - rois[bm*3+2];
        At[0][tid] = dx; At[1][tid] = dy; At[2][tid] = dz;
        const float4* f4 = (const float4*)(feats + ((size_t)b*NN + pidx)*CC);
        #pragma unroll
        for (int j = 0; j < 8; j++) {
            float4 v = emp ? make_float4(0,0,0,0) : f4[j];
            At[3+j*4+0][tid] = v.x; At[3+j*4+1][tid] = v.y;
            At[3+j*4+2][tid] = v.z; At[3+j*4+3][tid] = v.w;
        }
        float dist = sqrtf(dx*dx + dy*dy + dz*dz);
        float r = g_rad[b*RR + ((bm % MM) >> 6)];
        g_w[bm*NS2 + s] = emp ? 0.f : 1.f / (1.f + expf(-(r - dist) / td[0]));
    }
    __syncthreads();
    int m0 = (tid >> 3) * 4, c0 = (tid & 7) * 8;
    unsigned long long acc[4][4] = {};
    for (int k = 0; k < 35; k++) {
        float4 a = *(const float4*)&At[k][m0];
        const unsigned long long* wp = (const unsigned long long*)&Ws[k*64 + c0];
        unsigned long long w0 = wp[0], w1 = wp[1], w2 = wp[2], w3 = wp[3];
        float av[4] = { a.x, a.y, a.z, a.w };
        #pragma unroll
        for (int m = 0; m < 4; m++) {
            unsigned long long am = dup2(av[m]);
            fma2(acc[m][0], am, w0); fma2(acc[m][1], am, w1);
            fma2(acc[m][2], am, w2); fma2(acc[m][3], am, w3);
        }
    }
    float ps[8] = {0,0,0,0,0,0,0,0}, pq[8] = {0,0,0,0,0,0,0,0};
    #pragma unroll
    for (int m = 0; m < 4; m++) {
        int mm = m0 + m, bm = bmBase + (mm >> 5), s = mm & 31;
        U2 u[4]; float y[8];
        #pragma unroll
        for (int n = 0; n < 4; n++) { u[n].u = acc[m][n]; y[2*n] = u[n].f.x; y[2*n+1] = u[n].f.y; }
        *(float4*)&g_bufA[bm*2048 + s*64 + c0]     = make_float4(y[0], y[1], y[2], y[3]);
        *(float4*)&g_bufA[bm*2048 + s*64 + c0 + 4] = make_float4(y[4], y[5], y[6], y[7]);
        #pragma unroll
        for (int n = 0; n < 8; n++) { ps[n] += y[n]; pq[n] += y[n]*y[n]; }
    }
    #pragma unroll
    for (int n = 0; n < 8; n++) { atomicAdd(&ssum[c0+n], ps[n]); atomicAdd(&ssq[c0+n], pq[n]); }
    __syncthreads();
    if (tid < 64) { atomicAdd(&g_sum[2][tid], ssum[tid]); atomicAdd(&g_sq[2][tid], ssq[tid]); }
}

// -------- stage2 layer1: BN2+ReLU + conv 64->64 (2 bm/block, 4x8 tile) --------
__global__ void __launch_bounds__(128, 6)
k_conv_f1(const float* __restrict__ W, const float* __restrict__ gam, const float* __restrict__ bet) {
    __shared__ __align__(16) float At[64][68];
    __shared__ __align__(16) float Ws[64*64];
    __shared__ float ssum[64], ssq[64], s_sc[64], s_sh[64];
    int bmBase = blockIdx.x * 2;
    int tid = threadIdx.x;
    for (int i = tid; i < 4096; i += 128) Ws[i] = W[i];
    if (tid < 64) {
        ssum[tid] = 0.f; ssq[tid] = 0.f;
        float mean = g_sum[2][tid] * (1.f/CNT2);
        float var  = g_sq[2][tid] * (1.f/CNT2) - mean*mean;
        float sc   = gam[tid] * rsqrtf(var + EPS_C);
        s_sc[tid] = sc; s_sh[tid] = bet[tid] - mean*sc;
    }
    __syncthreads();
    for (int i = tid; i < 4096; i += 128) {
        int c = i & 63, m = i >> 6;
        At[c][m] = fmaxf(fmaf(g_bufA[bmBase*2048 + i], s_sc[c], s_sh[c]), 0.f);
    }
    __syncthreads();
    int m0 = (tid >> 3) * 4, c0 = (tid & 7) * 8;
    unsigned long long acc[4][4] = {};
    for (int k = 0; k < 64; k++) {
        float4 a = *(const float4*)&At[k][m0];
        const unsigned long long* wp = (const unsigned long long*)&Ws[k*64 + c0];
        unsigned long long w0 = wp[0], w1 = wp[1], w2 = wp[2], w3 = wp[3];
        float av[4] = { a.x, a.y, a.z, a.w };
        #pragma unroll
        for (int m = 0; m < 4; m++) {
            unsigned long long am = dup2(av[m]);
            fma2(acc[m][0], am, w0); fma2(acc[m][1], am, w1);
            fma2(acc[m][2], am, w2); fma2(acc[m][3], am, w3);
        }
    }
    float ps[8] = {0,0,0,0,0,0,0,0}, pq[8] = {0,0,0,0,0,0,0,0};
    #pragma unroll
    for (int m = 0; m < 4; m++) {
        int mm = m0 + m, bm = bmBase + (mm >> 5), s = mm & 31;
        U2 u[4]; float y[8];
        #pragma unroll
        for (int n = 0; n < 4; n++) { u[n].u = acc[m][n]; y[2*n] = u[n].f.x; y[2*n+1] = u[n].f.y; }
        *(float4*)&g_bufB[bm*2048 + s*64 + c0]     = make_float4(y[0], y[1], y[2], y[3]);
        *(float4*)&g_bufB[bm*2048 + s*64 + c0 + 4] = make_float4(y[4], y[5], y[6], y[7]);
        #pragma unroll
        for (int n = 0; n < 8; n++) { ps[n] += y[n]; pq[n] += y[n]*y[n]; }
    }
    #pragma unroll
    for (int n = 0; n < 8; n++) { atomicAdd(&ssum[c0+n], ps[n]); atomicAdd(&ssq[c0+n], pq[n]); }
    __syncthreads();
    if (tid < 64) { atomicAdd(&g_sum[3][tid], ssum[tid]); atomicAdd(&g_sq[3][tid], ssq[tid]); }
}

// -------- final: BN3+ReLU * w, max over samples --------
__global__ void k_out(float* __restrict__ out, const float* __restrict__ gam,
                      const float* __restrict__ bet) {
    __shared__ float s_sc[64], s_sh[64];
    int tid = threadIdx.x;
    if (tid < 64) {
        float mean = g_sum[3][tid] * (1.f/CNT2);
        float var  = g_sq[3][tid] * (1.f/CNT2) - mean*mean;
        float sc   = gam[tid] * rsqrtf(var + EPS_C);
        s_sc[tid] = sc; s_sh[tid] = bet[tid] - mean*sc;
    }
    __syncthreads();
    int c = tid & 63, bmL = tid >> 6;
    int bm = blockIdx.x * 4 + bmL;
    float sc = s_sc[c], sh = s_sh[c];
    float mx = -1e30f;
    #pragma unroll
    for (int s = 0; s < NS2; s++) {
        float v = fmaxf(fmaf(g_bufB[bm*2048 + s*64 + c], sc, sh), 0.f) * g_w[bm*NS2 + s];
        mx = fmaxf(mx, v);
    }
    out[BM*3 + bm*64 + c] = mx;
}

extern "C" void kernel_launch(void* const* d_in, const int* in_sizes, int n_in,
                              void* d_out, int out_size) {
    const float* xyz  = (const float*)d_in[0];
    const float* feats= (const float*)d_in[1];
    const float* rois = (const float*)d_in[2];
    const float* roif = (const float*)d_in[3];
    const float* td   = (const float*)d_in[4];
    const float* pw0  = (const float*)d_in[5];
    const float* pg0  = (const float*)d_in[6];
    const float* pb0  = (const float*)d_in[7];
    const float* pw1  = (const float*)d_in[8];
    const float* pg1  = (const float*)d_in[9];
    const float* pb1  = (const float*)d_in[10];
    const float* fw0  = (const float*)d_in[11];
    const float* fg0  = (const float*)d_in[12];
    const float* fb0  = (const float*)d_in[13];
    const float* fw1  = (const float*)d_in[14];
    const float* fg1  = (const float*)d_in[15];
    const float* fb1  = (const float*)d_in[16];
    const float* fcw  = (const float*)d_in[17];
    const float* fcb  = (const float*)d_in[18];
    float* out = (float*)d_out;

    cudaMemcpyAsync(out, rois, (size_t)BM*3*sizeof(float), cudaMemcpyDeviceToDevice, 0);

    k_prep<<<32, 512>>>(xyz);
    k_grid<<<1, 1024>>>();
    k_scatter<<<32, 512>>>();
    k_bq<<<BM/8, 256>>>(rois, NS1, 0);
    k_conv_p0<<<BM/8, 128>>>(feats, rois, pw0);
    k_conv_p1<<<BM/8, 128>>>(pw1, pg0, pb0);
    k_roi_fc<<<BB*RR, 256>>>(roif, fcw, fcb, pg1, pb1);
    k_bq<<<BM/8, 256>>>(rois, NS2, 1);
    k_conv_f0<<<BM/2, 128>>>(feats, rois, fw0, td);
    k_conv_f1<<<BM/2, 128>>>(fw1, fg0, fb0);
    k_out<<<BM/4, 256>>>(out, fg1, fb1);
}